// round 6
// baseline (speedup 1.0000x reference)
#include <cuda_runtime.h>
#include <math.h>
#include <stdint.h>

// LocalAtten: NI=128, ND=32, NH=4, nnei=120.
// Algebraic refactor: never materialize kv.
//   p[t,h,c] = sum_d Q[t,d*4+h] * Wkv[c, d*4+h]          (k folded into q)
//   l[t,h,j] = gg1[t,j,:] . p[t,h,:]
//   a = softmax-mask-sw(l)
//   u[t,h,:] = sum_j a[t,h,j] * gg1[t,j,:]
//   out[t,:] = sum_h u[t,h,:] @ W2_h + bh,  W2_h = Wv_h @ Wh_h (precomputed)
// Packed fp32x2 FMA (Blackwell FFMA2) everywhere, full fp32 precision.
// gg1 DMA is MASK-PREDICATED per neighbor row (masked rows contribute
// exactly nothing downstream), halving DRAM traffic.
// W2 staged through smem (cp.async) so each CTA reads it exactly once.

#define NIc 128
#define NDc 32
#define NHc 4
#define NNEI 120
#define KVW ((NDc + NIc) * NHc) /* 640 */
#define TPC 14                  /* tokens per CTA */
#define NTHR 512
#define INV_SQRT_ND 0.17677669529663687f
#define UTP 20 /* Ut row pad (floats): 16B-aligned rows, low bank conflict */

typedef unsigned long long u64;

// Precomputed fused output weights: W2[(h*128+c)*128 + o]
__device__ float W2g[NHc * NIc * NIc];

// ---------------- packed f32x2 helpers ----------------
__device__ __forceinline__ u64 pk2(float x, float y) {
    u64 r;
    asm("mov.b64 %0, {%1,%2};" : "=l"(r) : "f"(x), "f"(y));
    return r;
}
__device__ __forceinline__ void up2(u64 v, float& x, float& y) {
    asm("mov.b64 {%0,%1}, %2;" : "=f"(x), "=f"(y) : "l"(v));
}
__device__ __forceinline__ void fma2(u64& d, u64 a, u64 b) {
    asm("fma.rn.f32x2 %0, %1, %2, %0;" : "+l"(d) : "l"(a), "l"(b));
}

// ---------------- prep: W2[h*128+c][o] = sum_i Wv_h[c,i] * Wh[h*128+i, o] ----
__global__ void prep_w2_kernel(const float* __restrict__ Wkv,
                               const float* __restrict__ Wh) {
    __shared__ float wk[4 * NIc];
    int b = blockIdx.x;
    int h = b >> 5, c0 = (b & 31) * 4;
    int o = threadIdx.x;
#pragma unroll
    for (int cc = 0; cc < 4; cc++)
        wk[cc * NIc + o] = Wkv[(size_t)(c0 + cc) * KVW + NDc * NHc + o * NHc + h];
    __syncthreads();
    float acc[4] = {0.f, 0.f, 0.f, 0.f};
#pragma unroll 8
    for (int i = 0; i < NIc; i++) {
        float w = Wh[(size_t)(h * NIc + i) * NIc + o];
        acc[0] += wk[0 * NIc + i] * w;
        acc[1] += wk[1 * NIc + i] * w;
        acc[2] += wk[2 * NIc + i] * w;
        acc[3] += wk[3 * NIc + i] * w;
    }
#pragma unroll
    for (int cc = 0; cc < 4; cc++)
        W2g[(size_t)(h * NIc + c0 + cc) * NIc + o] = acc[cc];
}

// ---------------- cp.async ----------------
__device__ __forceinline__ void cpa16(float* dst, const float* src) {
    unsigned d = (unsigned)__cvta_generic_to_shared(dst);
    asm volatile("cp.async.cg.shared.global [%0], [%1], 16;\n" ::"r"(d), "l"(src));
}
// Mask-predicated gg1 tile load: 4 threads per neighbor row (128B each);
// masked rows are skipped entirely (their stale smem contents are never
// consumed: logits are skipped and attention weight is exactly 0).
__device__ __forceinline__ void load_gg1_tile_masked(float* buf, const float* src,
                                                     const float* mkrow, int tid) {
    int row = tid >> 2;  // 0..127 (>=120 idle)
    int q = tid & 3;
    if (row < NNEI && mkrow[row] != 0.f) {
        const float* s = src + row * NIc + q * 32;
        float* d = buf + row * NIc + q * 32;
#pragma unroll
        for (int i = 0; i < 8; i++) cpa16(d + i * 4, s + i * 4);
    }
}
// One 64-row W2 chunk: 8192 floats = 2048 float4s -> 4 per thread
__device__ __forceinline__ void load_w2_chunk(float* buf, int chunk, int tid) {
#pragma unroll
    for (int q = 0; q < 4; q++) {
        int idx = tid + q * NTHR;
        cpa16(buf + idx * 4, &W2g[(size_t)chunk * 8192 + idx * 4]);
    }
}

// smem layout (floats)
#define OFF_GB0 0
#define OFF_GB1 15360
#define OFF_QS 30720   /* 14*128  = 1792 */
#define OFF_PS 32512   /* 14*512  = 7168 */
#define OFF_LA 39680   /* 4*128   = 512  */
#define OFF_UT 40192   /* 512*20  = 10240 (Ut[k][t], transposed U) */
#define OFF_RED 50432  /* 8*512   = 4096 (u partials / G1 tile / C partials) */
#define OFF_SW 54528   /* 14*120  = 1680 (sw, prefetched) */
#define OFF_MK 56208   /* 14*120  = 1680 (mask as 0/1 float) */
#define SMEM_FLOATS 57888
#define SMEM_BYTES (SMEM_FLOATS * 4) /* 231552 <= 232448 cap */

__global__ __launch_bounds__(NTHR, 1) void localatten_kernel(
    const float* __restrict__ g1, const float* __restrict__ gg1,
    const void* __restrict__ maskp, const float* __restrict__ sw,
    const float* __restrict__ Wq, const float* __restrict__ Wkv,
    const float* __restrict__ bh, float* __restrict__ out, int ntok) {
    extern __shared__ __align__(16) float sm[];
    float* GB0 = sm + OFF_GB0;
    float* GB1 = sm + OFF_GB1;
    float* Qs  = sm + OFF_QS;
    float* Ps  = sm + OFF_PS;
    float* la  = sm + OFF_LA;   // [h*128 + j]
    float* Ut  = sm + OFF_UT;   // [k*UTP + t]
    float* red = sm + OFF_RED;
    float* SWs = sm + OFF_SW;   // [t*120 + j]
    float* Mk  = sm + OFF_MK;   // [t*120 + j], 0.0 or 1.0
    float* G1s = red;

    const int tid = threadIdx.x;
    const int tok0 = blockIdx.x * TPC;
    int tcount = ntok - tok0;
    if (tcount <= 0) return;
    if (tcount > TPC) tcount = TPC;
    const int nj = tcount * NNEI;

    // ---- mask dtype self-detection (4-byte {0,1,1.0f} vs packed bytes) ----
    int mmode;
    {
        const int* mi = (const int*)maskp;
        bool word = true;
#pragma unroll 8
        for (int i = 0; i < 64; i++) {
            int v = mi[i];
            if (v != 0 && v != 1 && v != 0x3f800000) word = false;
        }
        mmode = word ? 0 : 1;
    }

    // ---- sw slice prefetch (independent of mask; joins tile-0's group) ----
    {
        const float* swsrc = sw + (size_t)tok0 * NNEI;
        int nq = nj / 4;  // nj % 4 == 0 (120 per token), base 16B-aligned
        for (int q = tid; q < nq; q += NTHR)
            cpa16(SWs + q * 4, swsrc + q * 4);
    }

    // ---- mask -> smem as 0/1 float (needed BEFORE predicated tile load) ----
    {
        const size_t base = (size_t)tok0 * NNEI;
        if (mmode == 0) {
            const int* mi = (const int*)maskp + base;
            for (int i = tid; i < nj; i += NTHR) Mk[i] = (mi[i] != 0) ? 1.f : 0.f;
        } else {
            const unsigned char* mb = (const unsigned char*)maskp + base;
            for (int i = tid; i < nj; i += NTHR) Mk[i] = (mb[i] != 0) ? 1.f : 0.f;
        }
    }

    // ---- Phase A0: G1 tile into smem (reuses red) ----
    for (int idx = tid; idx < tcount * NIc; idx += NTHR)
        G1s[idx] = g1[(size_t)tok0 * NIc + idx];
    __syncthreads();  // Mk + G1s visible

    // ---- prefetch token 0's gg1 tile (mask-predicated) ----
    load_gg1_tile_masked(GB0, gg1 + (size_t)tok0 * NNEI * NIc, &Mk[0], tid);
    asm volatile("cp.async.commit_group;\n");  // group: sw slice + tile 0

    // ---- Phase A1: Q = G1 @ Wq  (Q[t][x], x = d*4+h) ----
    {
        int grp = tid >> 7, x = tid & 127;
        float acc[4] = {0.f, 0.f, 0.f, 0.f};
#pragma unroll 2
        for (int i = 0; i < NIc; i++) {
            float w = Wq[(size_t)i * NIc + x];
#pragma unroll
            for (int g2 = 0; g2 < 4; g2++)
                acc[g2] += G1s[(grp * 4 + g2) * NIc + i] * w;
        }
#pragma unroll
        for (int g2 = 0; g2 < 4; g2++) {
            int t = grp * 4 + g2;
            if (t < tcount) Qs[t * NIc + x] = acc[g2];
        }
    }
    __syncthreads();

    // ---- Phase A2: P[t][h][c] = sum_d Q[t][d*4+h] * Wkv[c][d*4+h] ----
    {
        int grp = tid >> 7, c = tid & 127;
        u64 pac[4][2];
#pragma unroll
        for (int g2 = 0; g2 < 4; g2++) pac[g2][0] = pac[g2][1] = 0ull;
#pragma unroll 4
        for (int d = 0; d < NDc; d++) {
            ulonglong2 w = *(const ulonglong2*)&Wkv[(size_t)c * KVW + d * 4];
#pragma unroll
            for (int g2 = 0; g2 < 4; g2++) {
                ulonglong2 q = *(const ulonglong2*)&Qs[(grp * 4 + g2) * NIc + d * 4];
                fma2(pac[g2][0], q.x, w.x);
                fma2(pac[g2][1], q.y, w.y);
            }
        }
#pragma unroll
        for (int g2 = 0; g2 < 4; g2++) {
            int t = grp * 4 + g2;
            if (t < tcount) {
                float p0, p1, p2, p3;
                up2(pac[g2][0], p0, p1);
                up2(pac[g2][1], p2, p3);
                Ps[(t * 4 + 0) * NIc + c] = p0;
                Ps[(t * 4 + 1) * NIc + c] = p1;
                Ps[(t * 4 + 2) * NIc + c] = p2;
                Ps[(t * 4 + 3) * NIc + c] = p3;
            }
        }
    }
    __syncthreads();

    const int warp = tid >> 5, lane = tid & 31;
    const int sub = lane & 7, jg = lane >> 3;
    const unsigned gmask = 0xFFu << (jg * 8);  // 8-lane shfl group

    // ---- Phase B: per-token attention ----
    for (int t = 0; t < tcount; t++) {
        if (t + 1 < tcount)
            load_gg1_tile_masked((t & 1) ? GB0 : GB1,
                                 gg1 + (size_t)(tok0 + t + 1) * NNEI * NIc,
                                 &Mk[(t + 1) * NNEI], tid);
        else  // last token: prefetch W2 chunk 0 into the free buffer
            load_w2_chunk((tcount & 1) ? GB1 : GB0, 0, tid);
        asm volatile("cp.async.commit_group;\n");
        asm volatile("cp.async.wait_group 1;\n");
        __syncthreads();

        const float* g = (t & 1) ? GB1 : GB0;

        // logits: 8-lane groups own swizzled 16-channel slices; 4 j per warp
        // per pass; 2 passes cover 120 j. la layout: la[h*128 + j].
        // Masked j are skipped entirely (softmax never reads their logit).
        {
            u64 ph[4][4][2];
#pragma unroll
            for (int h = 0; h < 4; h++)
#pragma unroll
                for (int k = 0; k < 4; k++) {
                    ulonglong2 v = *(const ulonglong2*)&Ps[(t * 4 + h) * NIc +
                                                           k * 32 + sub * 4];
                    ph[h][k][0] = v.x;
                    ph[h][k][1] = v.y;
                }
#pragma unroll
            for (int pass = 0; pass < 2; pass++) {
                int j = pass * 64 + warp * 4 + jg;
                bool act = (j < NNEI) && (Mk[t * NNEI + j] != 0.f);
                if (act) {
                    u64 s2[4] = {0ull, 0ull, 0ull, 0ull};
#pragma unroll
                    for (int k = 0; k < 4; k++) {
                        ulonglong2 gv =
                            *(const ulonglong2*)&g[j * NIc + k * 32 + sub * 4];
#pragma unroll
                        for (int h = 0; h < 4; h++) {
                            fma2(s2[h], gv.x, ph[h][k][0]);
                            fma2(s2[h], gv.y, ph[h][k][1]);
                        }
                    }
                    float s[4];
#pragma unroll
                    for (int h = 0; h < 4; h++) {
                        float lo, hi;
                        up2(s2[h], lo, hi);
                        s[h] = lo + hi;
                    }
#pragma unroll
                    for (int off = 4; off >= 1; off >>= 1) {
#pragma unroll
                        for (int h = 0; h < 4; h++)
                            s[h] += __shfl_xor_sync(gmask, s[h], off);
                    }
                    if (sub == 0) {
                        la[0 * NIc + j] = s[0];
                        la[1 * NIc + j] = s[1];
                        la[2 * NIc + j] = s[2];
                        la[3 * NIc + j] = s[3];
                    }
                }
            }
        }
        __syncthreads();

        // softmax + mask + sw from smem (warp h handles head h);
        // writes exact 0 at masked j.
        if (warp < 4) {
            int h = warp;
            const float* mrow = &Mk[t * NNEI];
            const float* srow = &SWs[t * NNEI];
            float v[4];
            int mskv[4];
            float swv[4];
            float mx = -INFINITY;
#pragma unroll
            for (int q2 = 0; q2 < 4; q2++) {
                int j = lane + q2 * 32;
                bool in = j < NNEI;
                mskv[q2] = in ? (mrow[j] != 0.f) : 0;
                swv[q2] = in ? srow[j] : 0.f;
                v[q2] = (in && mskv[q2]) ? la[h * NIc + j] * INV_SQRT_ND
                                         : -INFINITY;
                mx = fmaxf(mx, v[q2]);
            }
#pragma unroll
            for (int off = 16; off >= 1; off >>= 1)
                mx = fmaxf(mx, __shfl_xor_sync(0xffffffffu, mx, off));
            float e[4];
            float s = 0.f;
#pragma unroll
            for (int q2 = 0; q2 < 4; q2++) {
                e[q2] = mskv[q2] ? __expf(v[q2] - mx) : 0.f;
                s += e[q2];
            }
#pragma unroll
            for (int off = 16; off >= 1; off >>= 1)
                s += __shfl_xor_sync(0xffffffffu, s, off);
            float inv = (s > 0.f) ? (1.f / s) : 0.f;
#pragma unroll
            for (int q2 = 0; q2 < 4; q2++) {
                int j = lane + q2 * 32;
                la[h * NIc + j] = e[q2] * inv * swv[q2];
            }
        }
        __syncthreads();

        // u[h][c] = sum_j a[h][j] * g[j][c]
        // warp = (jblk 0..7) x (head pair hp 0..1); 15 j per jblk.
        // Masked j have a == 0 exactly -> warp-uniform skip (never touches
        // the stale smem rows the predicated DMA left behind).
        {
            const int jblk = warp >> 1;
            const int hp = warp & 1;
            u64 ua[2][2] = {{0ull, 0ull}, {0ull, 0ull}};
            const float* gb = g + jblk * 15 * NIc + lane * 4;
            const float* lab = la + hp * 2 * NIc + jblk * 15;
#pragma unroll 5
            for (int jj = 0; jj < 15; jj++) {
                float a0 = lab[jj];
                float a1 = lab[NIc + jj];
                if (a0 == 0.f && a1 == 0.f) continue;
                ulonglong2 gv = *(const ulonglong2*)(gb + jj * NIc);
                u64 ad0 = pk2(a0, a0);
                u64 ad1 = pk2(a1, a1);
                fma2(ua[0][0], gv.x, ad0);
                fma2(ua[0][1], gv.y, ad0);
                fma2(ua[1][0], gv.x, ad1);
                fma2(ua[1][1], gv.y, ad1);
            }
#pragma unroll
            for (int hh = 0; hh < 2; hh++) {
                ulonglong2 st;
                st.x = ua[hh][0];
                st.y = ua[hh][1];
                *(ulonglong2*)&red[jblk * 512 + (hp * 2 + hh) * NIc + lane * 4] = st;
            }
        }
        __syncthreads();

        // reduce 8 partials -> Ut[k][t] (transposed for Phase C)
        {
            float ssum = 0.f;
#pragma unroll
            for (int p = 0; p < 8; p++) ssum += red[p * 512 + tid];
            Ut[tid * UTP + t] = ssum;
        }
        __syncthreads();
    }

    // ---- Phase C: OUT[t][o] = bh[o] + sum_k Ut[k][t] * W2[k][o] ----
    // Thread = (o 0..127) x (token-group tg 0..1, 8 tokens) x (k-subhalf kh).
    // W2 staged via cp.async in 8 chunks of 64 rows, double-buffered.
    {
        const int o = tid & 127;
        const int tg = (tid >> 7) & 1;
        const int kh = tid >> 8;
        u64 acc[4] = {0ull, 0ull, 0ull, 0ull};
#pragma unroll 1
        for (int c = 0; c < 8; c++) {
            float* wbuf = ((tcount + c) & 1) ? GB1 : GB0;
            if (c + 1 < 8) {
                load_w2_chunk(((tcount + c + 1) & 1) ? GB1 : GB0, c + 1, tid);
                asm volatile("cp.async.commit_group;\n");
                asm volatile("cp.async.wait_group 1;\n");
            } else {
                asm volatile("cp.async.wait_group 0;\n");
            }
            __syncthreads();
            const float* wrow = wbuf + kh * 32 * NIc + o;
            const float* urow = &Ut[(c * 64 + kh * 32) * UTP + tg * 8];
#pragma unroll 8
            for (int kk = 0; kk < 32; kk++) {
                float w = wrow[kk * NIc];
                u64 wd = pk2(w, w);
                ulonglong2 uA = *(const ulonglong2*)(urow + kk * UTP);
                ulonglong2 uB = *(const ulonglong2*)(urow + kk * UTP + 4);
                fma2(acc[0], uA.x, wd);
                fma2(acc[1], uA.y, wd);
                fma2(acc[2], uB.x, wd);
                fma2(acc[3], uB.y, wd);
            }
            __syncthreads();  // protect wbuf before it becomes a prefetch target
        }

        // combine k-halves and store
        if (kh == 1) {
            ulonglong2 s0, s1;
            s0.x = acc[0]; s0.y = acc[1];
            s1.x = acc[2]; s1.y = acc[3];
            *(ulonglong2*)&red[(tid & 255) * 8] = s0;
            *(ulonglong2*)&red[(tid & 255) * 8 + 4] = s1;
        }
        __syncthreads();
        if (kh == 0) {
            float b = bh[o];
            const float* pr = &red[(tid & 255) * 8];
            float v[8];
            up2(acc[0], v[0], v[1]);
            up2(acc[1], v[2], v[3]);
            up2(acc[2], v[4], v[5]);
            up2(acc[3], v[6], v[7]);
#pragma unroll
            for (int tt = 0; tt < 8; tt++) {
                int t = tg * 8 + tt;
                if (t < tcount)
                    out[(size_t)(tok0 + t) * NIc + o] = v[tt] + pr[tt] + b;
            }
        }
    }
}

extern "C" void kernel_launch(void* const* d_in, const int* in_sizes, int n_in,
                              void* d_out, int out_size) {
    const float* g1  = (const float*)d_in[0];
    const float* gg1 = (const float*)d_in[1];
    const void*  msk = d_in[2];
    const float* sw  = (const float*)d_in[3];
    const float* Wq  = (const float*)d_in[4];
    const float* Wkv = (const float*)d_in[5];
    const float* Wh  = (const float*)d_in[6];
    const float* bh  = (const float*)d_in[7];
    float* out = (float*)d_out;

    int ntok = in_sizes[0] / NIc;  // nb*nloc

    prep_w2_kernel<<<128, 128>>>(Wkv, Wh);

    cudaFuncSetAttribute(localatten_kernel,
                         cudaFuncAttributeMaxDynamicSharedMemorySize, SMEM_BYTES);
    int grid = (ntok + TPC - 1) / TPC;
    localatten_kernel<<<grid, NTHR, SMEM_BYTES>>>(g1, gg1, msk, sw, Wq, Wkv, bh,
                                                  out, ntok);
}